// round 4
// baseline (speedup 1.0000x reference)
#include <cuda_runtime.h>
#include <cuda_bf16.h>
#include <stdint.h>

// Problem constants
#define BB 2
#define NN 16384
#define KK 32
#define FF 64
#define EE 16
#define NT (BB * NN)      // 32768 nodes
#define SK (FF * EE)      // 1024 = GEMM contraction length

// W2 split/transposed (tiny, precomputed by k_w2)
__device__ __align__(16) __nv_bfloat16 g_Bh[FF * SK];   // B[n][k] = w2^T hi
__device__ __align__(16) __nv_bfloat16 g_Bl[FF * SK];   // B[n][k] lo

// ---- packed f32x2 helpers ----
static __device__ __forceinline__ unsigned long long pk2(float x, float y) {
    unsigned long long r;
    asm("mov.b64 %0, {%1, %2};" : "=l"(r) : "f"(x), "f"(y));
    return r;
}
static __device__ __forceinline__ void upk2(unsigned long long v, float &x, float &y) {
    asm("mov.b64 {%0, %1}, %2;" : "=f"(x), "=f"(y) : "l"(v));
}
static __device__ __forceinline__ unsigned long long ffma2(
    unsigned long long a, unsigned long long b, unsigned long long c) {
    unsigned long long d;
    asm("fma.rn.f32x2 %0, %1, %2, %3;" : "=l"(d) : "l"(a), "l"(b), "l"(c));
    return d;
}
static __device__ __forceinline__ uint32_t bfpack(float hi, float lo) {
    uint32_t r;
    asm("cvt.rn.bf16x2.f32 %0, %1, %2;" : "=r"(r) : "f"(hi), "f"(lo));
    return r;
}

// ---- mma / ldmatrix (arch-portable HMMA; tcgen05 unavailable via compute_103) ----
static __device__ __forceinline__ uint32_t smem_u32(const void* p) {
    uint32_t a;
    asm("{ .reg .u64 t; cvta.to.shared.u64 t, %1; cvt.u32.u64 %0, t; }" : "=r"(a) : "l"(p));
    return a;
}
static __device__ __forceinline__ void ldsm4(uint32_t* r, uint32_t addr) {
    asm volatile("ldmatrix.sync.aligned.m8n8.x4.shared.b16 {%0,%1,%2,%3}, [%4];"
                 : "=r"(r[0]), "=r"(r[1]), "=r"(r[2]), "=r"(r[3]) : "r"(addr));
}
static __device__ __forceinline__ void mma16816(float* c, const uint32_t* a,
                                                const uint32_t* b) {
    asm volatile(
        "mma.sync.aligned.m16n8k16.row.col.f32.bf16.bf16.f32 "
        "{%0,%1,%2,%3}, {%4,%5,%6,%7}, {%8,%9}, {%0,%1,%2,%3};"
        : "+f"(c[0]), "+f"(c[1]), "+f"(c[2]), "+f"(c[3])
        : "r"(a[0]), "r"(a[1]), "r"(a[2]), "r"(a[3]), "r"(b[0]), "r"(b[1]));
}

// ---- kernel 0: W split/transpose: g_Bh/g_Bl[n][k] = split(w[l][n][e]), k=l*16+e ----
__global__ void k_w2(const float* __restrict__ w) {
    int id = blockIdx.x * blockDim.x + threadIdx.x;   // id = n*1024 + k
    if (id < FF * SK) {
        int n = id >> 10;
        int k = id & 1023;
        int l = k >> 4;
        int e = k & 15;
        float v = w[l * (FF * EE) + n * EE + e];
        __nv_bfloat16 h = __float2bfloat16(v);
        g_Bh[id] = h;
        g_Bl[id] = __float2bfloat16(v - __bfloat162float(h));
    }
}

// ================= fused kernel =================
// Block: 256 threads, 64 nodes. Loop over 8 l-chunks (k-chunk = 128):
//   phase1: FFMA2 outer-product accumulation of S-chunk in registers
//   (gathers hit L2-resident `nodes`); split to bf16 hi/lo into smem;
//   phase2: HMMA S-chunk @ W2-chunk, out accumulated in registers.
#define MT 64            // nodes per block
#define LCH 8            // l per chunk
#define KCH 128          // k per chunk
#define NCH 8            // chunks

// smem layout (bytes). Pitches padded to kill bank degeneracy.
#define EPITCH 516                          // floats per edge row (512 + 4 pad)
#define OFF_E    0
#define OFF_IDX  (MT * EPITCH * 4)          // 132096
#define IPITCH 36                           // ints per nlist row (32 + 4 pad)
#define OFF_SH   (OFF_IDX + MT * IPITCH * 4)   // 141312
#define SPITCHB 272                         // bytes per S/W2 row (128 halves + 8 pad)
#define OFF_SL   (OFF_SH + MT * SPITCHB)
#define OFF_WH   (OFF_SL + MT * SPITCHB)
#define OFF_WL   (OFF_WH + FF * SPITCHB)
#define SMEM_SZ  (OFF_WL + FF * SPITCHB)    // 210944

__global__ __launch_bounds__(256) void k_fused(
    const float* __restrict__ nodes,
    const int*   __restrict__ nlist,
    const float* __restrict__ edges,
    float* __restrict__ out)
{
    extern __shared__ __align__(16) char sm[];
    const int t    = threadIdx.x;
    const int lane = t & 31;
    const int wrp  = t >> 5;
    const int g0   = blockIdx.x * MT;
    const int b    = blockIdx.x >> 8;          // 512 blocks, batch flips at 256
    const uint32_t sb = smem_u32(sm);

    float* s_e   = reinterpret_cast<float*>(sm + OFF_E);
    int*   s_idx = reinterpret_cast<int*>(sm + OFF_IDX);

    // ---- phase 0: edges + nlist -> smem ----
    {
        const float4* ef = reinterpret_cast<const float4*>(edges) + (size_t)g0 * 128;
#pragma unroll
        for (int q = 0; q < 32; q++) {
            int u = q * 256 + t;               // 0..8191
            int node = u >> 7, v = u & 127;
            reinterpret_cast<float4*>(s_e)[node * (EPITCH / 4) + v] = ef[u];
        }
        const int4* nf = reinterpret_cast<const int4*>(nlist) + (size_t)g0 * 8;
#pragma unroll
        for (int q = 0; q < 2; q++) {
            int u = q * 256 + t;               // 0..511
            int node = u >> 3, v = u & 7;
            reinterpret_cast<int4*>(s_idx)[node * (IPITCH / 4) + v] = nf[u];
        }
    }
    __syncthreads();

    // phase1 mapping: 4 threads per node, each owns 2 l's of the 8-chunk
    const int p1_node = t >> 2;
    const int p1_sub  = t & 3;
    const float* nbase = nodes + (size_t)b * (NN * FF);
    const float* s_e_node = s_e + p1_node * EPITCH;
    const int*   s_idx_node = s_idx + p1_node * IPITCH;

    // phase2 mapping: warp -> (m-tile of 16 rows, n-half of 32 cols)
    const int mt = wrp >> 1;
    const int nh = wrp & 1;
    const int a_r = (lane & 7) + 8 * ((lane >> 3) & 1);
    const int a_k = (lane >> 4) * 8;
    const int b_n = 8 * (lane >> 4) + (lane & 7);
    const int b_k = 8 * ((lane >> 3) & 1);
    const uint32_t aAh = sb + OFF_SH + (mt * 16 + a_r) * SPITCHB + a_k * 2;
    const uint32_t aAl = sb + OFF_SL + (mt * 16 + a_r) * SPITCHB + a_k * 2;
    const uint32_t aBh = sb + OFF_WH + (nh * 32 + b_n) * SPITCHB + b_k * 2;
    const uint32_t aBl = sb + OFF_WL + (nh * 32 + b_n) * SPITCHB + b_k * 2;

    float oacc[4][4];
#pragma unroll
    for (int nt = 0; nt < 4; nt++)
#pragma unroll
        for (int i = 0; i < 4; i++) oacc[nt][i] = 0.0f;

    for (int c = 0; c < NCH; c++) {
        const int l0 = c * LCH;

        // ---- phase 1: accumulate S-chunk (2 l's x 16 n per thread) ----
        unsigned long long acc[2][8];
#pragma unroll
        for (int li = 0; li < 2; li++)
#pragma unroll
            for (int p = 0; p < 8; p++) acc[li][p] = 0ull;

        const float* gat = nbase + l0 + p1_sub * 2;
#pragma unroll 2
        for (int jg = 0; jg < KK; jg += 4) {
            int4 jdx4 = *reinterpret_cast<const int4*>(s_idx_node + jg);
            float2 a0 = *reinterpret_cast<const float2*>(gat + (size_t)jdx4.x * FF);
            float2 a1 = *reinterpret_cast<const float2*>(gat + (size_t)jdx4.y * FF);
            float2 a2 = *reinterpret_cast<const float2*>(gat + (size_t)jdx4.z * FF);
            float2 a3 = *reinterpret_cast<const float2*>(gat + (size_t)jdx4.w * FF);
            float2 av[4] = {a0, a1, a2, a3};
#pragma unroll
            for (int jj = 0; jj < 4; jj++) {
                const ulonglong2* ep =
                    reinterpret_cast<const ulonglong2*>(s_e_node + (jg + jj) * EE);
                unsigned long long ax = pk2(av[jj].x, av[jj].x);
                unsigned long long ay = pk2(av[jj].y, av[jj].y);
#pragma unroll
                for (int q = 0; q < 4; q++) {
                    ulonglong2 ev = ep[q];
                    acc[0][2 * q]     = ffma2(ax, ev.x, acc[0][2 * q]);
                    acc[0][2 * q + 1] = ffma2(ax, ev.y, acc[0][2 * q + 1]);
                    acc[1][2 * q]     = ffma2(ay, ev.x, acc[1][2 * q]);
                    acc[1][2 * q + 1] = ffma2(ay, ev.y, acc[1][2 * q + 1]);
                }
            }
        }

        __syncthreads();   // previous chunk's MMA done before overwriting s_S/s_W2

        // split to bf16 hi/lo, write S-chunk rows [node][k_local = l_local*16+n]
        const float sc = 1.0f / (float)KK;
#pragma unroll
        for (int li = 0; li < 2; li++) {
            uint32_t hu[8], lu[8];
#pragma unroll
            for (int p = 0; p < 8; p++) {
                float x, y;
                upk2(acc[li][p], x, y);
                x *= sc; y *= sc;
                uint32_t h = bfpack(y, x);
                float hx = __uint_as_float(h << 16);
                float hy = __uint_as_float(h & 0xffff0000u);
                hu[p] = h;
                lu[p] = bfpack(y - hy, x - hx);
            }
            int boff = p1_node * SPITCHB + (p1_sub * 2 + li) * 32;
            *reinterpret_cast<uint4*>(sm + OFF_SH + boff) =
                make_uint4(hu[0], hu[1], hu[2], hu[3]);
            *reinterpret_cast<uint4*>(sm + OFF_SH + boff + 16) =
                make_uint4(hu[4], hu[5], hu[6], hu[7]);
            *reinterpret_cast<uint4*>(sm + OFF_SL + boff) =
                make_uint4(lu[0], lu[1], lu[2], lu[3]);
            *reinterpret_cast<uint4*>(sm + OFF_SL + boff + 16) =
                make_uint4(lu[4], lu[5], lu[6], lu[7]);
        }

        // stage W2 chunk: [64 n][128 k_local] hi/lo
#pragma unroll
        for (int q = 0; q < 4; q++) {
            int u = q * 256 + t;               // 0..1023
            int n = u >> 4, kq = u & 15;
            int boff = n * SPITCHB + kq * 16;
            size_t src = (size_t)n * SK + c * KCH + kq * 8;
            *reinterpret_cast<uint4*>(sm + OFF_WH + boff) =
                *reinterpret_cast<const uint4*>(g_Bh + src);
            *reinterpret_cast<uint4*>(sm + OFF_WL + boff) =
                *reinterpret_cast<const uint4*>(g_Bl + src);
        }
        __syncthreads();

        // ---- phase 2: HMMA S-chunk @ W2-chunk ----
#pragma unroll
        for (int ks = 0; ks < KCH / 16; ks++) {
            const int kb = ks * 32;            // bytes
            uint32_t a_h[4], a_l[4];
            ldsm4(a_h, aAh + kb);
            ldsm4(a_l, aAl + kb);
            uint32_t bh[4][2], bl[4][2];
#pragma unroll
            for (int p = 0; p < 2; p++) {
                uint32_t r4[4];
                ldsm4(r4, aBh + p * 16 * SPITCHB + kb);
                bh[2 * p][0] = r4[0]; bh[2 * p][1] = r4[1];
                bh[2 * p + 1][0] = r4[2]; bh[2 * p + 1][1] = r4[3];
                ldsm4(r4, aBl + p * 16 * SPITCHB + kb);
                bl[2 * p][0] = r4[0]; bl[2 * p][1] = r4[1];
                bl[2 * p + 1][0] = r4[2]; bl[2 * p + 1][1] = r4[3];
            }
#pragma unroll
            for (int nt = 0; nt < 4; nt++) {
                mma16816(oacc[nt], a_h, bh[nt]);
                mma16816(oacc[nt], a_h, bl[nt]);
                mma16816(oacc[nt], a_l, bh[nt]);
            }
        }
    }

    // ---- epilogue ----
    const int row0 = g0 + mt * 16 + (lane >> 2);
    const int cb   = nh * 32 + 2 * (lane & 3);
#pragma unroll
    for (int nt = 0; nt < 4; nt++) {
        *reinterpret_cast<float2*>(out + (size_t)row0 * FF + cb + 8 * nt) =
            make_float2(oacc[nt][0], oacc[nt][1]);
        *reinterpret_cast<float2*>(out + (size_t)(row0 + 8) * FF + cb + 8 * nt) =
            make_float2(oacc[nt][2], oacc[nt][3]);
    }
}

extern "C" void kernel_launch(void* const* d_in, const int* in_sizes, int n_in,
                              void* d_out, int out_size) {
    const float* nodes = (const float*)d_in[0];
    const int*   nlist = (const int*)d_in[1];
    const float* edges = (const float*)d_in[2];
    const float* w     = (const float*)d_in[3];
    float* out = (float*)d_out;
    (void)in_sizes; (void)n_in; (void)out_size;

    cudaFuncSetAttribute(k_fused,
                         cudaFuncAttributeMaxDynamicSharedMemorySize, SMEM_SZ);

    k_w2<<<(FF * SK + 255) / 256, 256>>>(w);
    k_fused<<<NT / MT, 256, SMEM_SZ>>>(nodes, nlist, edges, out);
}

// round 5
// speedup vs baseline: 1.2993x; 1.2993x over previous
#include <cuda_runtime.h>
#include <cuda_bf16.h>
#include <stdint.h>

// Problem constants
#define BB 2
#define NN 16384
#define KK 32
#define FF 64
#define EE 16
#define NT (BB * NN)      // 32768 nodes
#define SK (FF * EE)      // 1024 = GEMM contraction length

// Scratch (static __device__ arrays — no runtime allocation)
__device__ __align__(16) __nv_bfloat16 g_Sh[(size_t)NT * SK];  // 64 MB: S hi
__device__ __align__(16) __nv_bfloat16 g_Sl[(size_t)NT * SK];  // 64 MB: S lo
__device__ __align__(16) __nv_bfloat16 g_Bh[FF * SK];          // B[n][k] = w2^T hi
__device__ __align__(16) __nv_bfloat16 g_Bl[FF * SK];          // B[n][k] lo

// ---- packed f32x2 helpers ----
static __device__ __forceinline__ unsigned long long pk2(float x, float y) {
    unsigned long long r;
    asm("mov.b64 %0, {%1, %2};" : "=l"(r) : "f"(x), "f"(y));
    return r;
}
static __device__ __forceinline__ void upk2(unsigned long long v, float &x, float &y) {
    asm("mov.b64 {%0, %1}, %2;" : "=f"(x), "=f"(y) : "l"(v));
}
static __device__ __forceinline__ unsigned long long ffma2(
    unsigned long long a, unsigned long long b, unsigned long long c) {
    unsigned long long d;
    asm("fma.rn.f32x2 %0, %1, %2, %3;" : "=l"(d) : "l"(a), "l"(b), "l"(c));
    return d;
}
static __device__ __forceinline__ uint32_t bfpack(float hi, float lo) {
    uint32_t r;
    asm("cvt.rn.bf16x2.f32 %0, %1, %2;" : "=r"(r) : "f"(hi), "f"(lo));
    return r;
}

// ---- mma / ldmatrix (arch-portable HMMA; tcgen05 unavailable via compute_103) ----
static __device__ __forceinline__ uint32_t smem_u32(const void* p) {
    uint32_t a;
    asm("{ .reg .u64 t; cvta.to.shared.u64 t, %1; cvt.u32.u64 %0, t; }" : "=r"(a) : "l"(p));
    return a;
}
static __device__ __forceinline__ void ldsm4(uint32_t* r, uint32_t addr) {
    asm volatile("ldmatrix.sync.aligned.m8n8.x4.shared.b16 {%0,%1,%2,%3}, [%4];"
                 : "=r"(r[0]), "=r"(r[1]), "=r"(r[2]), "=r"(r[3]) : "r"(addr));
}
static __device__ __forceinline__ void mma16816(float* c, const uint32_t* a,
                                                const uint32_t* b) {
    asm volatile(
        "mma.sync.aligned.m16n8k16.row.col.f32.bf16.bf16.f32 "
        "{%0,%1,%2,%3}, {%4,%5,%6,%7}, {%8,%9}, {%0,%1,%2,%3};"
        : "+f"(c[0]), "+f"(c[1]), "+f"(c[2]), "+f"(c[3])
        : "r"(a[0]), "r"(a[1]), "r"(a[2]), "r"(a[3]), "r"(b[0]), "r"(b[1]));
}

// ---- kernel 0: W split/transpose: g_Bh/g_Bl[n][k] = split(w[l][n][e]), k=l*16+e ----
__global__ void k_w2(const float* __restrict__ w) {
    int id = blockIdx.x * blockDim.x + threadIdx.x;   // id = n*1024 + k
    if (id < FF * SK) {
        int n = id >> 10;
        int k = id & 1023;
        int l = k >> 4;
        int e = k & 15;
        float v = w[l * (FF * EE) + n * EE + e];
        __nv_bfloat16 h = __float2bfloat16(v);
        g_Bh[id] = h;
        g_Bl[id] = __float2bfloat16(v - __bfloat162float(h));
    }
}

// ---- kernel 1: per-node S[l][n] = (1/K) * sum_j sliced[j][l] * edges[j][n] ----
// 1 warp per node; lane owns l-pair (2*lane, 2*lane+1) x 16 n as 16 f32x2 accs.
// Edge rows + nlist staged in smem; all stage-loop LDS are warp-broadcast.
#define S1N 8            // nodes per 256-thread block
#define S1_EP 129        // float4 pitch per edge row (128 + 1 pad)

__global__ __launch_bounds__(256) void k_stage1(
    const float* __restrict__ nodes,
    const int*   __restrict__ nlist,
    const float* __restrict__ edges)
{
    __shared__ __align__(16) float4 s_e[S1N * S1_EP];
    __shared__ __align__(16) int    s_idx[S1N][KK];

    const int t    = threadIdx.x;
    const int warp = t >> 5;
    const int lane = t & 31;
    const int g0   = blockIdx.x * S1N;
    const int g    = g0 + warp;
    const int b    = g >> 14;

    // stage edges (8 nodes x 128 float4) + nlist (8 x 32)
    {
        const float4* ef = reinterpret_cast<const float4*>(edges) + (size_t)g0 * 128;
#pragma unroll
        for (int q = 0; q < 4; q++) {
            int u = q * 256 + t;               // 0..1023
            int node = u >> 7, v = u & 127;
            s_e[node * S1_EP + v] = ef[u];
        }
        if (t < 64) {
            reinterpret_cast<int4*>(s_idx)[ (t >> 3) * 8 + (t & 7) ] =
                reinterpret_cast<const int4*>(nlist + (size_t)g0 * KK)[t];
        }
    }
    __syncthreads();

    const float* nb = nodes + (size_t)b * (NN * FF) + lane * 2;
    const float* en = reinterpret_cast<const float*>(s_e + warp * S1_EP);

    unsigned long long acc[16];
#pragma unroll
    for (int p = 0; p < 16; p++) acc[p] = 0ull;

#pragma unroll
    for (int jg = 0; jg < KK; jg += 4) {
        int4 jdx = *reinterpret_cast<const int4*>(&s_idx[warp][jg]);  // broadcast
        float2 a0 = *reinterpret_cast<const float2*>(nb + (size_t)jdx.x * FF);
        float2 a1 = *reinterpret_cast<const float2*>(nb + (size_t)jdx.y * FF);
        float2 a2 = *reinterpret_cast<const float2*>(nb + (size_t)jdx.z * FF);
        float2 a3 = *reinterpret_cast<const float2*>(nb + (size_t)jdx.w * FF);
        float2 av[4] = {a0, a1, a2, a3};
#pragma unroll
        for (int jj = 0; jj < 4; jj++) {
            const ulonglong2* ep =
                reinterpret_cast<const ulonglong2*>(en + (jg + jj) * EE);
            unsigned long long ax = pk2(av[jj].x, av[jj].x);
            unsigned long long ay = pk2(av[jj].y, av[jj].y);
#pragma unroll
            for (int q = 0; q < 4; q++) {                 // broadcast LDS.128
                ulonglong2 ev = ep[q];
                acc[2 * q]         = ffma2(ax, ev.x, acc[2 * q]);
                acc[2 * q + 1]     = ffma2(ax, ev.y, acc[2 * q + 1]);
                acc[8 + 2 * q]     = ffma2(ay, ev.x, acc[8 + 2 * q]);
                acc[8 + 2 * q + 1] = ffma2(ay, ev.y, acc[8 + 2 * q + 1]);
            }
        }
    }

    // scale, split bf16 hi/lo, store; lane covers k = lane*32 .. lane*32+31
    const float sc = 1.0f / (float)KK;
#pragma unroll
    for (int li = 0; li < 2; li++) {
        uint32_t hu[8], lu[8];
#pragma unroll
        for (int p = 0; p < 8; p++) {
            float x, y;
            upk2(acc[li * 8 + p], x, y);
            x *= sc; y *= sc;
            uint32_t h = bfpack(y, x);
            float hx = __uint_as_float(h << 16);
            float hy = __uint_as_float(h & 0xffff0000u);
            hu[p] = h;
            lu[p] = bfpack(y - hy, x - hx);
        }
        size_t off = (size_t)g * SK + lane * 32 + li * 16;
        *reinterpret_cast<uint4*>(g_Sh + off)     = make_uint4(hu[0], hu[1], hu[2], hu[3]);
        *reinterpret_cast<uint4*>(g_Sh + off + 8) = make_uint4(hu[4], hu[5], hu[6], hu[7]);
        *reinterpret_cast<uint4*>(g_Sl + off)     = make_uint4(lu[0], lu[1], lu[2], lu[3]);
        *reinterpret_cast<uint4*>(g_Sl + off + 8) = make_uint4(lu[4], lu[5], lu[6], lu[7]);
    }
}

// ---- kernel 2: HMMA GEMM out[32768 x 64] = S @ W2 (split-bf16, 3 products) ----
// (unchanged from round-3 passing version)
#define KC 64
#define APITCH 72
#define SM_A_H 0
#define SM_A_L (128 * APITCH * 2)            // 18432
#define SM_B_H (2 * 128 * APITCH * 2)        // 36864
#define SM_B_L (SM_B_H + 64 * APITCH * 2)    // 46080
#define SMEM2_SZ (SM_B_L + 64 * APITCH * 2)  // 55296

__global__ __launch_bounds__(256) void k_stage2(float* __restrict__ out)
{
    extern __shared__ __align__(16) char sm[];
    const int t    = threadIdx.x;
    const int w    = t >> 5;
    const int lane = t & 31;
    const int m0   = blockIdx.x * 128;
    const uint32_t sb = smem_u32(sm);

    const int a_r = (lane & 7) + ((lane >> 3) & 1) * 8;
    const int a_k = (lane >> 4) * 8;
    const int b_n = 8 * (lane >> 4) + (lane & 7);
    const int b_k = 8 * ((lane >> 3) & 1);
    const uint32_t aAh = sb + SM_A_H + (w * 16 + a_r) * 144 + a_k * 2;
    const uint32_t aAl = sb + SM_A_L + (w * 16 + a_r) * 144 + a_k * 2;
    const uint32_t aBh = sb + SM_B_H + b_n * 144 + b_k * 2;
    const uint32_t aBl = sb + SM_B_L + b_n * 144 + b_k * 2;

    const int ar = t >> 3;
    const int aj = t & 7;

    float acc[8][4];
#pragma unroll
    for (int nt = 0; nt < 8; nt++)
#pragma unroll
        for (int i = 0; i < 4; i++) acc[nt][i] = 0.0f;

    for (int c = 0; c < SK / KC; c++) {
        const int kk = c * KC;
        uint4 ra_h[4], ra_l[4], rb_h[2], rb_l[2];
#pragma unroll
        for (int q = 0; q < 4; q++) {
            size_t src = (size_t)(m0 + ar + 32 * q) * SK + kk + aj * 8;
            ra_h[q] = *reinterpret_cast<const uint4*>(g_Sh + src);
            ra_l[q] = *reinterpret_cast<const uint4*>(g_Sl + src);
        }
#pragma unroll
        for (int q = 0; q < 2; q++) {
            size_t src = (size_t)(ar + 32 * q) * SK + kk + aj * 8;
            rb_h[q] = *reinterpret_cast<const uint4*>(g_Bh + src);
            rb_l[q] = *reinterpret_cast<const uint4*>(g_Bl + src);
        }
        __syncthreads();
#pragma unroll
        for (int q = 0; q < 4; q++) {
            int boff = (ar + 32 * q) * 144 + aj * 16;
            *reinterpret_cast<uint4*>(sm + SM_A_H + boff) = ra_h[q];
            *reinterpret_cast<uint4*>(sm + SM_A_L + boff) = ra_l[q];
        }
#pragma unroll
        for (int q = 0; q < 2; q++) {
            int boff = (ar + 32 * q) * 144 + aj * 16;
            *reinterpret_cast<uint4*>(sm + SM_B_H + boff) = rb_h[q];
            *reinterpret_cast<uint4*>(sm + SM_B_L + boff) = rb_l[q];
        }
        __syncthreads();

#pragma unroll
        for (int ks = 0; ks < 4; ks++) {
            const int kb2 = ks * 32;
            uint32_t a_h[4], a_l[4];
            ldsm4(a_h, aAh + kb2);
            ldsm4(a_l, aAl + kb2);
            uint32_t bh[8][2], bl[8][2];
#pragma unroll
            for (int p = 0; p < 4; p++) {
                uint32_t r4[4];
                ldsm4(r4, aBh + p * 16 * 144 + kb2);
                bh[2 * p][0] = r4[0]; bh[2 * p][1] = r4[1];
                bh[2 * p + 1][0] = r4[2]; bh[2 * p + 1][1] = r4[3];
                ldsm4(r4, aBl + p * 16 * 144 + kb2);
                bl[2 * p][0] = r4[0]; bl[2 * p][1] = r4[1];
                bl[2 * p + 1][0] = r4[2]; bl[2 * p + 1][1] = r4[3];
            }
#pragma unroll
            for (int nt = 0; nt < 8; nt++) {
                mma16816(acc[nt], a_h, bh[nt]);
                mma16816(acc[nt], a_h, bl[nt]);
                mma16816(acc[nt], a_l, bh[nt]);
            }
        }
    }

    const int row0 = m0 + w * 16 + (lane >> 2);
    const int cb   = 2 * (lane & 3);
#pragma unroll
    for (int nt = 0; nt < 8; nt++) {
        *reinterpret_cast<float2*>(out + (size_t)row0 * FF + 8 * nt + cb) =
            make_float2(acc[nt][0], acc[nt][1]);
        *reinterpret_cast<float2*>(out + (size_t)(row0 + 8) * FF + 8 * nt + cb) =
            make_float2(acc[nt][2], acc[nt][3]);
    }
}

extern "C" void kernel_launch(void* const* d_in, const int* in_sizes, int n_in,
                              void* d_out, int out_size) {
    const float* nodes = (const float*)d_in[0];
    const int*   nlist = (const int*)d_in[1];
    const float* edges = (const float*)d_in[2];
    const float* w     = (const float*)d_in[3];
    float* out = (float*)d_out;
    (void)in_sizes; (void)n_in; (void)out_size;

    cudaFuncSetAttribute(k_stage2,
                         cudaFuncAttributeMaxDynamicSharedMemorySize, SMEM2_SZ);

    k_w2<<<(FF * SK + 255) / 256, 256>>>(w);
    k_stage1<<<NT / S1N, 256>>>(nodes, nlist, edges);
    k_stage2<<<NT / 128, 256, SMEM2_SZ>>>(out);
}

// round 7
// speedup vs baseline: 1.3383x; 1.0301x over previous
#include <cuda_runtime.h>
#include <cuda_bf16.h>
#include <stdint.h>

// Problem constants
#define BB 2
#define NN 16384
#define KK 32
#define FF 64
#define EE 16
#define NT (BB * NN)      // 32768 nodes
#define SK (FF * EE)      // 1024 = GEMM contraction length

// Scratch (static __device__ arrays — no runtime allocation)
__device__ __align__(16) __nv_bfloat16 g_Sh[(size_t)NT * SK];  // 64 MB: S hi
__device__ __align__(16) __nv_bfloat16 g_Sl[(size_t)NT * SK];  // 64 MB: S lo
__device__ __align__(16) __nv_bfloat16 g_Bh[FF * SK];          // B[n][k] = w2^T hi
__device__ __align__(16) __nv_bfloat16 g_Bl[FF * SK];          // B[n][k] lo

static __device__ __forceinline__ uint32_t bfpack(float hi, float lo) {
    uint32_t r;
    asm("cvt.rn.bf16x2.f32 %0, %1, %2;" : "=r"(r) : "f"(hi), "f"(lo));
    return r;
}
static __device__ __forceinline__ uint32_t smem_u32(const void* p) {
    uint32_t a;
    asm("{ .reg .u64 t; cvta.to.shared.u64 t, %1; cvt.u32.u64 %0, t; }" : "=r"(a) : "l"(p));
    return a;
}
static __device__ __forceinline__ void ldsm4(uint32_t* r, uint32_t addr) {
    asm volatile("ldmatrix.sync.aligned.m8n8.x4.shared.b16 {%0,%1,%2,%3}, [%4];"
                 : "=r"(r[0]), "=r"(r[1]), "=r"(r[2]), "=r"(r[3]) : "r"(addr));
}
static __device__ __forceinline__ void ldsm4t(uint32_t* r, uint32_t addr) {
    asm volatile("ldmatrix.sync.aligned.m8n8.x4.trans.shared.b16 {%0,%1,%2,%3}, [%4];"
                 : "=r"(r[0]), "=r"(r[1]), "=r"(r[2]), "=r"(r[3]) : "r"(addr));
}
static __device__ __forceinline__ void mma16816(float* c, const uint32_t* a,
                                                const uint32_t* b) {
    asm volatile(
        "mma.sync.aligned.m16n8k16.row.col.f32.bf16.bf16.f32 "
        "{%0,%1,%2,%3}, {%4,%5,%6,%7}, {%8,%9}, {%0,%1,%2,%3};"
        : "+f"(c[0]), "+f"(c[1]), "+f"(c[2]), "+f"(c[3])
        : "r"(a[0]), "r"(a[1]), "r"(a[2]), "r"(a[3]), "r"(b[0]), "r"(b[1]));
}
// split float4 into packed bf16x2 hi (h01,h23) and lo (l01,l23)
static __device__ __forceinline__ void split4(float4 v, uint2& h, uint2& l) {
    uint32_t h01 = bfpack(v.y, v.x);
    uint32_t h23 = bfpack(v.w, v.z);
    float hx = __uint_as_float(h01 << 16);
    float hy = __uint_as_float(h01 & 0xffff0000u);
    float hz = __uint_as_float(h23 << 16);
    float hw = __uint_as_float(h23 & 0xffff0000u);
    h = make_uint2(h01, h23);
    l = make_uint2(bfpack(v.y - hy, v.x - hx), bfpack(v.w - hw, v.z - hz));
}

// ---- kernel 0: W split/transpose: g_Bh/g_Bl[n][k] = split(w[l][n][e]), k=l*16+e ----
__global__ void k_w2(const float* __restrict__ w) {
    int id = blockIdx.x * blockDim.x + threadIdx.x;   // id = n*1024 + k
    if (id < FF * SK) {
        int n = id >> 10;
        int k = id & 1023;
        int l = k >> 4;
        int e = k & 15;
        float v = w[l * (FF * EE) + n * EE + e];
        __nv_bfloat16 h = __float2bfloat16(v);
        g_Bh[id] = h;
        g_Bl[id] = __float2bfloat16(v - __bfloat162float(h));
    }
}

// ---- kernel 1 (tensor): per node, S[64l][16n] = sum_j G[j][l] * (E[j][n]/32) ----
// One warp per node. G gathered coalesced (each lane: 2 float4 per row-pass ->
// full 64-float rows), split bf16 hi/lo into warp-private smem; E likewise
// (1/32 folded, exact). ldmatrix.trans + 48 HMMA (GhEh + GhEl + GlEh).
#define S1NODES 8
#define GP 144                    // G row pitch bytes (128 data + 16 pad)
#define EP 48                     // E row pitch bytes (32 data + 16 pad)
#define GBYTES (32 * GP)          // 4608
#define EBYTES (32 * EP)          // 1536
#define NODE_SM (2 * GBYTES + 2 * EBYTES)   // 12288
#define S1SMEM (S1NODES * NODE_SM)          // 98304

__global__ __launch_bounds__(256) void k_stage1(
    const float* __restrict__ nodes,
    const int*   __restrict__ nlist,
    const float* __restrict__ edges)
{
    extern __shared__ __align__(16) char sm1[];
    const int t    = threadIdx.x;
    const int warp = t >> 5;
    const int lane = t & 31;
    const int g    = blockIdx.x * S1NODES + warp;
    const int b    = g >> 14;

    char* base = sm1 + warp * NODE_SM;
    const uint32_t sb = smem_u32(base);

    const int my_idx = nlist[(size_t)g * KK + lane];
    const float* nbase = nodes + (size_t)b * (NN * FF);

    // ---- gather G: 32 rows x 64 floats; 8 lanes per row, 4 rows per pass,
    //      each lane covers float4 l4 and l4+8 (both halves of the row) ----
    const int l4   = lane & 7;     // float4 column within row (low half)
    const int rsub = lane >> 3;    // row within 4-row pass
#pragma unroll
    for (int h = 0; h < 2; h++) {
        float4 vlo[4], vhi[4];
#pragma unroll
        for (int p = 0; p < 4; p++) {
            int j = h * 16 + p * 4 + rsub;
            int jdx = __shfl_sync(0xffffffffu, my_idx, j);
            const float* rp = nbase + (size_t)jdx * FF;
            vlo[p] = *reinterpret_cast<const float4*>(rp + l4 * 4);
            vhi[p] = *reinterpret_cast<const float4*>(rp + l4 * 4 + 32);
        }
#pragma unroll
        for (int p = 0; p < 4; p++) {
            int j = h * 16 + p * 4 + rsub;
            uint2 hh, ll;
            int off = j * GP + l4 * 8;
            split4(vlo[p], hh, ll);
            *reinterpret_cast<uint2*>(base + off)               = hh;
            *reinterpret_cast<uint2*>(base + GBYTES + off)      = ll;
            split4(vhi[p], hh, ll);
            *reinterpret_cast<uint2*>(base + off + 64)          = hh;
            *reinterpret_cast<uint2*>(base + GBYTES + off + 64) = ll;
        }
    }
    // ---- E: 32 rows x 16 floats, scaled by 1/32 (exact), split hi/lo ----
    {
        const float4* ef = reinterpret_cast<const float4*>(edges) + (size_t)g * 128;
#pragma unroll
        for (int q = 0; q < 4; q++) {
            int u = q * 32 + lane;           // 0..127
            float4 v = ef[u];
            v.x *= 0.03125f; v.y *= 0.03125f; v.z *= 0.03125f; v.w *= 0.03125f;
            uint2 hh, ll;
            split4(v, hh, ll);
            int j = u >> 2, n4 = u & 3;
            int off = 2 * GBYTES + j * EP + n4 * 8;
            *reinterpret_cast<uint2*>(base + off)          = hh;
            *reinterpret_cast<uint2*>(base + EBYTES + off) = ll;
        }
    }
    __syncwarp();

    // ldmatrix.trans addresses (derived from PTX fragment layouts):
    // A (m=l, k=j) from G[j][l]: row = (lane&7)+8*(lane>>4), colbyte = ((lane>>3)&1)*16
    // B (k=j, n=n) from E[j][n]: row = (lane&7)+8*((lane>>3)&1), colbyte = (lane>>4)*16
    const uint32_t aA = sb + ((lane & 7) + 8 * (lane >> 4)) * GP
                           + ((lane >> 3) & 1) * 16;
    const uint32_t aB = sb + 2 * GBYTES
                           + ((lane & 7) + 8 * ((lane >> 3) & 1)) * EP
                           + (lane >> 4) * 16;

    float C[4][2][4];
#pragma unroll
    for (int mt = 0; mt < 4; mt++)
#pragma unroll
        for (int nt = 0; nt < 2; nt++)
#pragma unroll
            for (int i = 0; i < 4; i++) C[mt][nt][i] = 0.0f;

#pragma unroll
    for (int ks = 0; ks < 2; ks++) {
        uint32_t bh[4], bl[4];                       // [0..1]=ntile0, [2..3]=ntile1
        ldsm4t(bh, aB + ks * 16 * EP);
        ldsm4t(bl, aB + ks * 16 * EP + EBYTES);
#pragma unroll
        for (int mt = 0; mt < 4; mt++) {
            uint32_t ah[4], al[4];
            ldsm4t(ah, aA + ks * 16 * GP + mt * 32);
            ldsm4t(al, aA + ks * 16 * GP + mt * 32 + GBYTES);
#pragma unroll
            for (int nt = 0; nt < 2; nt++) {
                mma16816(C[mt][nt], ah, bh + nt * 2);
                mma16816(C[mt][nt], ah, bl + nt * 2);
                mma16816(C[mt][nt], al, bh + nt * 2);
            }
        }
    }

    // ---- epilogue: C[mt][nt] pairs land at contiguous k = l*16 + n ----
    const int r = lane >> 2, q = lane & 3;
    __nv_bfloat16* shp = g_Sh + (size_t)g * SK;
    __nv_bfloat16* slp = g_Sl + (size_t)g * SK;
#pragma unroll
    for (int mt = 0; mt < 4; mt++) {
#pragma unroll
        for (int nt = 0; nt < 2; nt++) {
            int k0 = (mt * 16 + r) * 16 + nt * 8 + 2 * q;       // (c0,c1)
            int k1 = k0 + 128;                                  // rows +8 (c2,c3)
            float c0 = C[mt][nt][0], c1 = C[mt][nt][1];
            float c2 = C[mt][nt][2], c3 = C[mt][nt][3];
            uint32_t h0 = bfpack(c1, c0);
            uint32_t l0 = bfpack(c1 - __uint_as_float(h0 & 0xffff0000u),
                                 c0 - __uint_as_float(h0 << 16));
            uint32_t h1 = bfpack(c3, c2);
            uint32_t l1 = bfpack(c3 - __uint_as_float(h1 & 0xffff0000u),
                                 c2 - __uint_as_float(h1 << 16));
            *reinterpret_cast<uint32_t*>(shp + k0) = h0;
            *reinterpret_cast<uint32_t*>(slp + k0) = l0;
            *reinterpret_cast<uint32_t*>(shp + k1) = h1;
            *reinterpret_cast<uint32_t*>(slp + k1) = l1;
        }
    }
}

// ---- kernel 2: HMMA GEMM out[32768 x 64] = S @ W2 (unchanged, proven) ----
#define KC 64
#define APITCH 72
#define SM_A_H 0
#define SM_A_L (128 * APITCH * 2)            // 18432
#define SM_B_H (2 * 128 * APITCH * 2)        // 36864
#define SM_B_L (SM_B_H + 64 * APITCH * 2)    // 46080
#define SMEM2_SZ (SM_B_L + 64 * APITCH * 2)  // 55296

__global__ __launch_bounds__(256) void k_stage2(float* __restrict__ out)
{
    extern __shared__ __align__(16) char sm[];
    const int t    = threadIdx.x;
    const int w    = t >> 5;
    const int lane = t & 31;
    const int m0   = blockIdx.x * 128;
    const uint32_t sb = smem_u32(sm);

    const int a_r = (lane & 7) + ((lane >> 3) & 1) * 8;
    const int a_k = (lane >> 4) * 8;
    const int b_n = 8 * (lane >> 4) + (lane & 7);
    const int b_k = 8 * ((lane >> 3) & 1);
    const uint32_t aAh = sb + SM_A_H + (w * 16 + a_r) * 144 + a_k * 2;
    const uint32_t aAl = sb + SM_A_L + (w * 16 + a_r) * 144 + a_k * 2;
    const uint32_t aBh = sb + SM_B_H + b_n * 144 + b_k * 2;
    const uint32_t aBl = sb + SM_B_L + b_n * 144 + b_k * 2;

    const int ar = t >> 3;
    const int aj = t & 7;

    float acc[8][4];
#pragma unroll
    for (int nt = 0; nt < 8; nt++)
#pragma unroll
        for (int i = 0; i < 4; i++) acc[nt][i] = 0.0f;

    for (int c = 0; c < SK / KC; c++) {
        const int kk = c * KC;
        uint4 ra_h[4], ra_l[4], rb_h[2], rb_l[2];
#pragma unroll
        for (int q = 0; q < 4; q++) {
            size_t src = (size_t)(m0 + ar + 32 * q) * SK + kk + aj * 8;
            ra_h[q] = *reinterpret_cast<const uint4*>(g_Sh + src);
            ra_l[q] = *reinterpret_cast<const uint4*>(g_Sl + src);
        }
#pragma unroll
        for (int q = 0; q < 2; q++) {
            size_t src = (size_t)(ar + 32 * q) * SK + kk + aj * 8;
            rb_h[q] = *reinterpret_cast<const uint4*>(g_Bh + src);
            rb_l[q] = *reinterpret_cast<const uint4*>(g_Bl + src);
        }
        __syncthreads();
#pragma unroll
        for (int q = 0; q < 4; q++) {
            int boff = (ar + 32 * q) * 144 + aj * 16;
            *reinterpret_cast<uint4*>(sm + SM_A_H + boff) = ra_h[q];
            *reinterpret_cast<uint4*>(sm + SM_A_L + boff) = ra_l[q];
        }
#pragma unroll
        for (int q = 0; q < 2; q++) {
            int boff = (ar + 32 * q) * 144 + aj * 16;
            *reinterpret_cast<uint4*>(sm + SM_B_H + boff) = rb_h[q];
            *reinterpret_cast<uint4*>(sm + SM_B_L + boff) = rb_l[q];
        }
        __syncthreads();

#pragma unroll
        for (int ks = 0; ks < 4; ks++) {
            const int kb2 = ks * 32;
            uint32_t a_h[4], a_l[4];
            ldsm4(a_h, aAh + kb2);
            ldsm4(a_l, aAl + kb2);
            uint32_t bh[8][2], bl[8][2];
#pragma unroll
            for (int p = 0; p < 4; p++) {
                uint32_t r4[4];
                ldsm4(r4, aBh + p * 16 * 144 + kb2);
                bh[2 * p][0] = r4[0]; bh[2 * p][1] = r4[1];
                bh[2 * p + 1][0] = r4[2]; bh[2 * p + 1][1] = r4[3];
                ldsm4(r4, aBl + p * 16 * 144 + kb2);
                bl[2 * p][0] = r4[0]; bl[2 * p][1] = r4[1];
                bl[2 * p + 1][0] = r4[2]; bl[2 * p + 1][1] = r4[3];
            }
#pragma unroll
            for (int nt = 0; nt < 8; nt++) {
                mma16816(acc[nt], a_h, bh[nt]);
                mma16816(acc[nt], a_h, bl[nt]);
                mma16816(acc[nt], a_l, bh[nt]);
            }
        }
    }

    const int row0 = m0 + w * 16 + (lane >> 2);
    const int cb   = 2 * (lane & 3);
#pragma unroll
    for (int nt = 0; nt < 8; nt++) {
        *reinterpret_cast<float2*>(out + (size_t)row0 * FF + 8 * nt + cb) =
            make_float2(acc[nt][0], acc[nt][1]);
        *reinterpret_cast<float2*>(out + (size_t)(row0 + 8) * FF + 8 * nt + cb) =
            make_float2(acc[nt][2], acc[nt][3]);
    }
}

extern "C" void kernel_launch(void* const* d_in, const int* in_sizes, int n_in,
                              void* d_out, int out_size) {
    const float* nodes = (const float*)d_in[0];
    const int*   nlist = (const int*)d_in[1];
    const float* edges = (const float*)d_in[2];
    const float* w     = (const float*)d_in[3];
    float* out = (float*)d_out;
    (void)in_sizes; (void)n_in; (void)out_size;

    cudaFuncSetAttribute(k_stage1,
                         cudaFuncAttributeMaxDynamicSharedMemorySize, S1SMEM);
    cudaFuncSetAttribute(k_stage2,
                         cudaFuncAttributeMaxDynamicSharedMemorySize, SMEM2_SZ);

    k_w2<<<(FF * SK + 255) / 256, 256>>>(w);
    k_stage1<<<NT / S1NODES, 256, S1SMEM>>>(nodes, nlist, edges);
    k_stage2<<<NT / 128, 256, SMEM2_SZ>>>(out);
}

// round 8
// speedup vs baseline: 1.6488x; 1.2320x over previous
#include <cuda_runtime.h>
#include <cuda_bf16.h>
#include <cuda_fp16.h>
#include <stdint.h>

// Problem constants
#define BB 2
#define NN 16384
#define KK 32
#define FF 64
#define EE 16
#define NT (BB * NN)      // 32768 nodes
#define SK (FF * EE)      // 1024 = GEMM contraction length

// Scratch (static __device__ arrays — no runtime allocation)
__device__ __align__(16) __half g_S[(size_t)NT * SK];   // 64 MB: S (fp16)
__device__ __align__(16) __half g_Bh[FF * SK];          // B[n][k] = w2^T hi (fp16)
__device__ __align__(16) __half g_Bl[FF * SK];          // B[n][k] lo (fp16 residual)

static __device__ __forceinline__ uint32_t bfpack(float hi, float lo) {
    uint32_t r;
    asm("cvt.rn.bf16x2.f32 %0, %1, %2;" : "=r"(r) : "f"(hi), "f"(lo));
    return r;
}
static __device__ __forceinline__ uint32_t hfpack(float hi, float lo) {
    uint32_t r;
    asm("cvt.rn.f16x2.f32 %0, %1, %2;" : "=r"(r) : "f"(hi), "f"(lo));
    return r;
}
static __device__ __forceinline__ uint32_t smem_u32(const void* p) {
    uint32_t a;
    asm("{ .reg .u64 t; cvta.to.shared.u64 t, %1; cvt.u32.u64 %0, t; }" : "=r"(a) : "l"(p));
    return a;
}
static __device__ __forceinline__ void ldsm4(uint32_t* r, uint32_t addr) {
    asm volatile("ldmatrix.sync.aligned.m8n8.x4.shared.b16 {%0,%1,%2,%3}, [%4];"
                 : "=r"(r[0]), "=r"(r[1]), "=r"(r[2]), "=r"(r[3]) : "r"(addr));
}
static __device__ __forceinline__ void ldsm4t(uint32_t* r, uint32_t addr) {
    asm volatile("ldmatrix.sync.aligned.m8n8.x4.trans.shared.b16 {%0,%1,%2,%3}, [%4];"
                 : "=r"(r[0]), "=r"(r[1]), "=r"(r[2]), "=r"(r[3]) : "r"(addr));
}
static __device__ __forceinline__ void mma16816(float* c, const uint32_t* a,
                                                const uint32_t* b) {
    asm volatile(
        "mma.sync.aligned.m16n8k16.row.col.f32.bf16.bf16.f32 "
        "{%0,%1,%2,%3}, {%4,%5,%6,%7}, {%8,%9}, {%0,%1,%2,%3};"
        : "+f"(c[0]), "+f"(c[1]), "+f"(c[2]), "+f"(c[3])
        : "r"(a[0]), "r"(a[1]), "r"(a[2]), "r"(a[3]), "r"(b[0]), "r"(b[1]));
}
static __device__ __forceinline__ void mma16816h(float* c, const uint32_t* a,
                                                 const uint32_t* b) {
    asm volatile(
        "mma.sync.aligned.m16n8k16.row.col.f32.f16.f16.f32 "
        "{%0,%1,%2,%3}, {%4,%5,%6,%7}, {%8,%9}, {%0,%1,%2,%3};"
        : "+f"(c[0]), "+f"(c[1]), "+f"(c[2]), "+f"(c[3])
        : "r"(a[0]), "r"(a[1]), "r"(a[2]), "r"(a[3]), "r"(b[0]), "r"(b[1]));
}
// split float4 into packed bf16x2 hi (h01,h23) and lo (l01,l23)
static __device__ __forceinline__ void split4(float4 v, uint2& h, uint2& l) {
    uint32_t h01 = bfpack(v.y, v.x);
    uint32_t h23 = bfpack(v.w, v.z);
    float hx = __uint_as_float(h01 << 16);
    float hy = __uint_as_float(h01 & 0xffff0000u);
    float hz = __uint_as_float(h23 << 16);
    float hw = __uint_as_float(h23 & 0xffff0000u);
    h = make_uint2(h01, h23);
    l = make_uint2(bfpack(v.y - hy, v.x - hx), bfpack(v.w - hw, v.z - hz));
}

// ---- kernel 1 (tensor): per node, S[64l][16n] = sum_j G[j][l] * (E[j][n]/32) ----
// One warp per node; split-bf16 3-product HMMA; epilogue packs fp16 S via smem
// staging -> fully coalesced STG.128. Blocks 0..63 also perform the W2
// split/transpose (consumed only by k_stage2, launched after).
#define S1NODES 8
#define GP 144                    // G row pitch bytes (128 data + 16 pad)
#define EP 48                     // E row pitch bytes (32 data + 16 pad)
#define GBYTES (32 * GP)          // 4608
#define EBYTES (32 * EP)          // 1536
#define NODE_SM (2 * GBYTES + 2 * EBYTES)   // 12288
#define S1SMEM (S1NODES * NODE_SM)          // 98304

__global__ __launch_bounds__(256) void k_stage1(
    const float* __restrict__ nodes,
    const int*   __restrict__ nlist,
    const float* __restrict__ edges,
    const float* __restrict__ w)
{
    extern __shared__ __align__(16) char sm1[];
    const int t    = threadIdx.x;
    const int warp = t >> 5;
    const int lane = t & 31;
    const int g    = blockIdx.x * S1NODES + warp;
    const int b    = g >> 14;

    // ---- folded W2 split/transpose: g_Bh/g_Bl[n][k] = split(w[l][n][e]) ----
    if (blockIdx.x < 64) {
        int id0 = blockIdx.x * 1024 + t;
#pragma unroll
        for (int i = 0; i < 4; i++) {
            int id = id0 + i * 256;           // id = n*1024 + k
            int n = id >> 10;
            int k = id & 1023;
            int l = k >> 4;
            int e = k & 15;
            float v = w[l * (FF * EE) + n * EE + e];
            __half h = __float2half(v);
            g_Bh[id] = h;
            g_Bl[id] = __float2half(v - __half2float(h));
        }
    }

    char* base = sm1 + warp * NODE_SM;
    const uint32_t sb = smem_u32(base);

    const int my_idx = nlist[(size_t)g * KK + lane];
    const float* nbase = nodes + (size_t)b * (NN * FF);

    // ---- gather G: 32 rows x 64 floats; 8 lanes per row, 4 rows per pass,
    //      each lane covers float4 l4 and l4+8 (both halves of the row) ----
    const int l4   = lane & 7;
    const int rsub = lane >> 3;
#pragma unroll
    for (int h = 0; h < 2; h++) {
        float4 vlo[4], vhi[4];
#pragma unroll
        for (int p = 0; p < 4; p++) {
            int j = h * 16 + p * 4 + rsub;
            int jdx = __shfl_sync(0xffffffffu, my_idx, j);
            const float* rp = nbase + (size_t)jdx * FF;
            vlo[p] = *reinterpret_cast<const float4*>(rp + l4 * 4);
            vhi[p] = *reinterpret_cast<const float4*>(rp + l4 * 4 + 32);
        }
#pragma unroll
        for (int p = 0; p < 4; p++) {
            int j = h * 16 + p * 4 + rsub;
            uint2 hh, ll;
            int off = j * GP + l4 * 8;
            split4(vlo[p], hh, ll);
            *reinterpret_cast<uint2*>(base + off)               = hh;
            *reinterpret_cast<uint2*>(base + GBYTES + off)      = ll;
            split4(vhi[p], hh, ll);
            *reinterpret_cast<uint2*>(base + off + 64)          = hh;
            *reinterpret_cast<uint2*>(base + GBYTES + off + 64) = ll;
        }
    }
    // ---- E: 32 rows x 16 floats, scaled by 1/32 (exact), split hi/lo ----
    {
        const float4* ef = reinterpret_cast<const float4*>(edges) + (size_t)g * 128;
#pragma unroll
        for (int q = 0; q < 4; q++) {
            int u = q * 32 + lane;
            float4 v = ef[u];
            v.x *= 0.03125f; v.y *= 0.03125f; v.z *= 0.03125f; v.w *= 0.03125f;
            uint2 hh, ll;
            split4(v, hh, ll);
            int j = u >> 2, n4 = u & 3;
            int off = 2 * GBYTES + j * EP + n4 * 8;
            *reinterpret_cast<uint2*>(base + off)          = hh;
            *reinterpret_cast<uint2*>(base + EBYTES + off) = ll;
        }
    }
    __syncwarp();

    // ldmatrix.trans addresses (PTX fragment layouts):
    // A (m=l, k=j) from G[j][l]; B (k=j, n=n) from E[j][n]
    const uint32_t aA = sb + ((lane & 7) + 8 * (lane >> 4)) * GP
                           + ((lane >> 3) & 1) * 16;
    const uint32_t aB = sb + 2 * GBYTES
                           + ((lane & 7) + 8 * ((lane >> 3) & 1)) * EP
                           + (lane >> 4) * 16;

    float C[4][2][4];
#pragma unroll
    for (int mt = 0; mt < 4; mt++)
#pragma unroll
        for (int nt = 0; nt < 2; nt++)
#pragma unroll
            for (int i = 0; i < 4; i++) C[mt][nt][i] = 0.0f;

#pragma unroll
    for (int ks = 0; ks < 2; ks++) {
        uint32_t bh[4], bl[4];
        ldsm4t(bh, aB + ks * 16 * EP);
        ldsm4t(bl, aB + ks * 16 * EP + EBYTES);
#pragma unroll
        for (int mt = 0; mt < 4; mt++) {
            uint32_t ah[4], al[4];
            ldsm4t(ah, aA + ks * 16 * GP + mt * 32);
            ldsm4t(al, aA + ks * 16 * GP + mt * 32 + GBYTES);
#pragma unroll
            for (int nt = 0; nt < 2; nt++) {
                mma16816(C[mt][nt], ah, bh + nt * 2);
                mma16816(C[mt][nt], ah, bl + nt * 2);
                mma16816(C[mt][nt], al, bh + nt * 2);
            }
        }
    }

    // ---- epilogue: pack fp16, stage in smem, coalesced STG.128 ----
    __syncwarp();                       // all ldsm reads of E region done
    __half* sstage = reinterpret_cast<__half*>(base + 2 * GBYTES);
    const int r = lane >> 2, q = lane & 3;
#pragma unroll
    for (int mt = 0; mt < 4; mt++) {
#pragma unroll
        for (int nt = 0; nt < 2; nt++) {
            int k0 = (mt * 16 + r) * 16 + nt * 8 + 2 * q;       // (c0,c1)
            *reinterpret_cast<uint32_t*>(sstage + k0) =
                hfpack(C[mt][nt][1], C[mt][nt][0]);
            *reinterpret_cast<uint32_t*>(sstage + k0 + 128) =
                hfpack(C[mt][nt][3], C[mt][nt][2]);
        }
    }
    __syncwarp();
    {
        uint4* dst = reinterpret_cast<uint4*>(g_S + (size_t)g * SK);
        const uint4* src = reinterpret_cast<const uint4*>(sstage);
#pragma unroll
        for (int u = 0; u < 4; u++)
            dst[u * 32 + lane] = src[u * 32 + lane];
    }
}

// ---- kernel 2: HMMA GEMM out[32768 x 64] = S(fp16) @ W2 (fp16 hi+lo, 2 products) ----
#define KC 64
#define APITCH 72
#define SM_A   0
#define SM_B_H (128 * APITCH * 2)            // 18432
#define SM_B_L (SM_B_H + 64 * APITCH * 2)    // 27648
#define SMEM2_SZ (SM_B_L + 64 * APITCH * 2)  // 36864

__global__ __launch_bounds__(256) void k_stage2(float* __restrict__ out)
{
    extern __shared__ __align__(16) char sm[];
    const int t    = threadIdx.x;
    const int w    = t >> 5;
    const int lane = t & 31;
    const int m0   = blockIdx.x * 128;
    const uint32_t sb = smem_u32(sm);

    const int a_r = (lane & 7) + ((lane >> 3) & 1) * 8;
    const int a_k = (lane >> 4) * 8;
    const int b_n = 8 * (lane >> 4) + (lane & 7);
    const int b_k = 8 * ((lane >> 3) & 1);
    const uint32_t aA  = sb + SM_A   + (w * 16 + a_r) * 144 + a_k * 2;
    const uint32_t aBh = sb + SM_B_H + b_n * 144 + b_k * 2;
    const uint32_t aBl = sb + SM_B_L + b_n * 144 + b_k * 2;

    const int ar = t >> 3;
    const int aj = t & 7;

    float acc[8][4];
#pragma unroll
    for (int nt = 0; nt < 8; nt++)
#pragma unroll
        for (int i = 0; i < 4; i++) acc[nt][i] = 0.0f;

    for (int c = 0; c < SK / KC; c++) {
        const int kk = c * KC;
        uint4 ra[4], rb_h[2], rb_l[2];
#pragma unroll
        for (int q = 0; q < 4; q++) {
            size_t src = (size_t)(m0 + ar + 32 * q) * SK + kk + aj * 8;
            ra[q] = *reinterpret_cast<const uint4*>(g_S + src);
        }
#pragma unroll
        for (int q = 0; q < 2; q++) {
            size_t src = (size_t)(ar + 32 * q) * SK + kk + aj * 8;
            rb_h[q] = *reinterpret_cast<const uint4*>(g_Bh + src);
            rb_l[q] = *reinterpret_cast<const uint4*>(g_Bl + src);
        }
        __syncthreads();
#pragma unroll
        for (int q = 0; q < 4; q++)
            *reinterpret_cast<uint4*>(sm + SM_A + (ar + 32 * q) * 144 + aj * 16) = ra[q];
#pragma unroll
        for (int q = 0; q < 2; q++) {
            int boff = (ar + 32 * q) * 144 + aj * 16;
            *reinterpret_cast<uint4*>(sm + SM_B_H + boff) = rb_h[q];
            *reinterpret_cast<uint4*>(sm + SM_B_L + boff) = rb_l[q];
        }
        __syncthreads();

#pragma unroll
        for (int ks = 0; ks < 4; ks++) {
            const int kb2 = ks * 32;
            uint32_t a_h[4];
            ldsm4(a_h, aA + kb2);
            uint32_t bh[8][2], bl[8][2];
#pragma unroll
            for (int p = 0; p < 4; p++) {
                uint32_t r4[4];
                ldsm4(r4, aBh + p * 16 * 144 + kb2);
                bh[2 * p][0] = r4[0]; bh[2 * p][1] = r4[1];
                bh[2 * p + 1][0] = r4[2]; bh[2 * p + 1][1] = r4[3];
                ldsm4(r4, aBl + p * 16 * 144 + kb2);
                bl[2 * p][0] = r4[0]; bl[2 * p][1] = r4[1];
                bl[2 * p + 1][0] = r4[2]; bl[2 * p + 1][1] = r4[3];
            }
#pragma unroll
            for (int nt = 0; nt < 8; nt++) {
                mma16816h(acc[nt], a_h, bh[nt]);
                mma16816h(acc[nt], a_h, bl[nt]);
            }
        }
    }

    const int row0 = m0 + w * 16 + (lane >> 2);
    const int cb   = 2 * (lane & 3);
#pragma unroll
    for (int nt = 0; nt < 8; nt++) {
        *reinterpret_cast<float2*>(out + (size_t)row0 * FF + 8 * nt + cb) =
            make_float2(acc[nt][0], acc[nt][1]);
        *reinterpret_cast<float2*>(out + (size_t)(row0 + 8) * FF + 8 * nt + cb) =
            make_float2(acc[nt][2], acc[nt][3]);
    }
}

extern "C" void kernel_launch(void* const* d_in, const int* in_sizes, int n_in,
                              void* d_out, int out_size) {
    const float* nodes = (const float*)d_in[0];
    const int*   nlist = (const int*)d_in[1];
    const float* edges = (const float*)d_in[2];
    const float* w     = (const float*)d_in[3];
    float* out = (float*)d_out;
    (void)in_sizes; (void)n_in; (void)out_size;

    cudaFuncSetAttribute(k_stage1,
                         cudaFuncAttributeMaxDynamicSharedMemorySize, S1SMEM);
    cudaFuncSetAttribute(k_stage2,
                         cudaFuncAttributeMaxDynamicSharedMemorySize, SMEM2_SZ);

    k_stage1<<<NT / S1NODES, 256, S1SMEM>>>(nodes, nlist, edges, w);
    k_stage2<<<NT / 128, 256, SMEM2_SZ>>>(out);
}

// round 9
// speedup vs baseline: 2.3174x; 1.4055x over previous
#include <cuda_runtime.h>
#include <cuda_fp16.h>
#include <stdint.h>

// Problem constants
#define BB 2
#define NN 16384
#define KK 32
#define FF 64
#define EE 16
#define NT (BB * NN)      // 32768 nodes
#define SK (FF * EE)      // 1024 = GEMM contraction length

// Scratch (static __device__ arrays — no runtime allocation)
__device__ __align__(16) __half g_S[(size_t)NT * SK];   // 64 MB: S (fp16)
__device__ __align__(16) __half g_B[FF * SK];           // B[n][k] = w2^T (fp16)

static __device__ __forceinline__ uint32_t hfpack(float hi, float lo) {
    uint32_t r;
    asm("cvt.rn.f16x2.f32 %0, %1, %2;" : "=r"(r) : "f"(hi), "f"(lo));
    return r;
}
static __device__ __forceinline__ uint32_t smem_u32(const void* p) {
    uint32_t a;
    asm("{ .reg .u64 t; cvta.to.shared.u64 t, %1; cvt.u32.u64 %0, t; }" : "=r"(a) : "l"(p));
    return a;
}
static __device__ __forceinline__ void ldsm4(uint32_t* r, uint32_t addr) {
    asm volatile("ldmatrix.sync.aligned.m8n8.x4.shared.b16 {%0,%1,%2,%3}, [%4];"
                 : "=r"(r[0]), "=r"(r[1]), "=r"(r[2]), "=r"(r[3]) : "r"(addr));
}
static __device__ __forceinline__ void ldsm4t(uint32_t* r, uint32_t addr) {
    asm volatile("ldmatrix.sync.aligned.m8n8.x4.trans.shared.b16 {%0,%1,%2,%3}, [%4];"
                 : "=r"(r[0]), "=r"(r[1]), "=r"(r[2]), "=r"(r[3]) : "r"(addr));
}
static __device__ __forceinline__ void mma16816h(float* c, const uint32_t* a,
                                                 const uint32_t* b) {
    asm volatile(
        "mma.sync.aligned.m16n8k16.row.col.f32.f16.f16.f32 "
        "{%0,%1,%2,%3}, {%4,%5,%6,%7}, {%8,%9}, {%0,%1,%2,%3};"
        : "+f"(c[0]), "+f"(c[1]), "+f"(c[2]), "+f"(c[3])
        : "r"(a[0]), "r"(a[1]), "r"(a[2]), "r"(a[3]), "r"(b[0]), "r"(b[1]));
}

// ---- kernel 1 (tensor): per node, S[64l][16n] = sum_j G[j][l] * (E[j][n]/32) ----
// One warp per node; single-product fp16 HMMA (error budget verified R8).
// Blocks 0..63 also perform the W2 fp16 transpose (consumed only by k_stage2).
#define S1NODES 8
#define GP 144                    // G row pitch bytes (128 data + 16 pad)
#define EP 48                     // E row pitch bytes (32 data + 16 pad)
#define GBYTES (32 * GP)          // 4608
#define EBYTES (32 * EP)          // 1536
#define NODE_SM (GBYTES + EBYTES)           // 6144
#define S1SMEM (S1NODES * NODE_SM)          // 49152

__global__ __launch_bounds__(256) void k_stage1(
    const float* __restrict__ nodes,
    const int*   __restrict__ nlist,
    const float* __restrict__ edges,
    const float* __restrict__ w)
{
    extern __shared__ __align__(16) char sm1[];
    const int t    = threadIdx.x;
    const int warp = t >> 5;
    const int lane = t & 31;
    const int g    = blockIdx.x * S1NODES + warp;
    const int b    = g >> 14;

    // ---- folded W2 transpose: g_B[n][k] = fp16(w[l][n][e]), k = l*16+e ----
    if (blockIdx.x < 64) {
        int id0 = blockIdx.x * 1024 + t;
#pragma unroll
        for (int i = 0; i < 4; i++) {
            int id = id0 + i * 256;           // id = n*1024 + k
            int n = id >> 10;
            int k = id & 1023;
            int l = k >> 4;
            int e = k & 15;
            g_B[id] = __float2half(w[l * (FF * EE) + n * EE + e]);
        }
    }

    char* base = sm1 + warp * NODE_SM;
    const uint32_t sb = smem_u32(base);

    const int my_idx = nlist[(size_t)g * KK + lane];
    const float* nbase = nodes + (size_t)b * (NN * FF);

    // ---- gather G: 32 rows x 64 floats -> fp16; 8 lanes per row, 4 rows/pass,
    //      each lane covers float4 l4 and l4+8 (both halves of the row) ----
    const int l4   = lane & 7;
    const int rsub = lane >> 3;
#pragma unroll
    for (int h = 0; h < 2; h++) {
        float4 vlo[4], vhi[4];
#pragma unroll
        for (int p = 0; p < 4; p++) {
            int j = h * 16 + p * 4 + rsub;
            int jdx = __shfl_sync(0xffffffffu, my_idx, j);
            const float* rp = nbase + (size_t)jdx * FF;
            vlo[p] = *reinterpret_cast<const float4*>(rp + l4 * 4);
            vhi[p] = *reinterpret_cast<const float4*>(rp + l4 * 4 + 32);
        }
#pragma unroll
        for (int p = 0; p < 4; p++) {
            int j = h * 16 + p * 4 + rsub;
            int off = j * GP + l4 * 8;
            *reinterpret_cast<uint2*>(base + off) =
                make_uint2(hfpack(vlo[p].y, vlo[p].x), hfpack(vlo[p].w, vlo[p].z));
            *reinterpret_cast<uint2*>(base + off + 64) =
                make_uint2(hfpack(vhi[p].y, vhi[p].x), hfpack(vhi[p].w, vhi[p].z));
        }
    }
    // ---- E: 32 rows x 16 floats, scaled by 1/32 (exact), fp16 ----
    {
        const float4* ef = reinterpret_cast<const float4*>(edges) + (size_t)g * 128;
#pragma unroll
        for (int q = 0; q < 4; q++) {
            int u = q * 32 + lane;
            float4 v = ef[u];
            int j = u >> 2, n4 = u & 3;
            *reinterpret_cast<uint2*>(base + GBYTES + j * EP + n4 * 8) =
                make_uint2(hfpack(v.y * 0.03125f, v.x * 0.03125f),
                           hfpack(v.w * 0.03125f, v.z * 0.03125f));
        }
    }
    __syncwarp();

    // ldmatrix.trans addresses (PTX fragment layouts):
    // A (m=l, k=j) from G[j][l]; B (k=j, n=n) from E[j][n]
    const uint32_t aA = sb + ((lane & 7) + 8 * (lane >> 4)) * GP
                           + ((lane >> 3) & 1) * 16;
    const uint32_t aB = sb + GBYTES
                           + ((lane & 7) + 8 * ((lane >> 3) & 1)) * EP
                           + (lane >> 4) * 16;

    float C[4][2][4];
#pragma unroll
    for (int mt = 0; mt < 4; mt++)
#pragma unroll
        for (int nt = 0; nt < 2; nt++)
#pragma unroll
            for (int i = 0; i < 4; i++) C[mt][nt][i] = 0.0f;

#pragma unroll
    for (int ks = 0; ks < 2; ks++) {
        uint32_t bh[4];                       // [0..1]=ntile0, [2..3]=ntile1
        ldsm4t(bh, aB + ks * 16 * EP);
#pragma unroll
        for (int mt = 0; mt < 4; mt++) {
            uint32_t ah[4];
            ldsm4t(ah, aA + ks * 16 * GP + mt * 32);
            mma16816h(C[mt][0], ah, bh);
            mma16816h(C[mt][1], ah, bh + 2);
        }
    }

    // ---- epilogue: pack fp16, stage in smem (reuse G region), STG.128 ----
    __syncwarp();
    __half* sstage = reinterpret_cast<__half*>(base);
    const int r = lane >> 2, q = lane & 3;
#pragma unroll
    for (int mt = 0; mt < 4; mt++) {
#pragma unroll
        for (int nt = 0; nt < 2; nt++) {
            int k0 = (mt * 16 + r) * 16 + nt * 8 + 2 * q;       // (c0,c1)
            *reinterpret_cast<uint32_t*>(sstage + k0) =
                hfpack(C[mt][nt][1], C[mt][nt][0]);
            *reinterpret_cast<uint32_t*>(sstage + k0 + 128) =
                hfpack(C[mt][nt][3], C[mt][nt][2]);
        }
    }
    __syncwarp();
    {
        uint4* dst = reinterpret_cast<uint4*>(g_S + (size_t)g * SK);
        const uint4* src = reinterpret_cast<const uint4*>(sstage);
#pragma unroll
        for (int u = 0; u < 4; u++)
            dst[u * 32 + lane] = src[u * 32 + lane];
    }
}

// ---- kernel 2: HMMA GEMM out[32768 x 64] = S(fp16) @ W2(fp16), single product ----
#define KC 64
#define SM_A   0
#define SM_B   (128 * 144)                   // 18432
#define SMEM2_SZ (SM_B + 64 * 144)           // 27648

__global__ __launch_bounds__(256) void k_stage2(float* __restrict__ out)
{
    extern __shared__ __align__(16) char sm[];
    const int t    = threadIdx.x;
    const int w    = t >> 5;
    const int lane = t & 31;
    const int m0   = blockIdx.x * 128;
    const uint32_t sb = smem_u32(sm);

    const int a_r = (lane & 7) + ((lane >> 3) & 1) * 8;
    const int a_k = (lane >> 4) * 8;
    const int b_n = 8 * (lane >> 4) + (lane & 7);
    const int b_k = 8 * ((lane >> 3) & 1);
    const uint32_t aA = sb + SM_A + (w * 16 + a_r) * 144 + a_k * 2;
    const uint32_t aB = sb + SM_B + b_n * 144 + b_k * 2;

    const int ar = t >> 3;
    const int aj = t & 7;

    float acc[8][4];
#pragma unroll
    for (int nt = 0; nt < 8; nt++)
#pragma unroll
        for (int i = 0; i < 4; i++) acc[nt][i] = 0.0f;

    for (int c = 0; c < SK / KC; c++) {
        const int kk = c * KC;
        uint4 ra[4], rb[2];
#pragma unroll
        for (int q = 0; q < 4; q++) {
            size_t src = (size_t)(m0 + ar + 32 * q) * SK + kk + aj * 8;
            ra[q] = *reinterpret_cast<const uint4*>(g_S + src);
        }
#pragma unroll
        for (int q = 0; q < 2; q++) {
            size_t src = (size_t)(ar + 32 * q) * SK + kk + aj * 8;
            rb[q] = *reinterpret_cast<const uint4*>(g_B + src);
        }
        __syncthreads();
#pragma unroll
        for (int q = 0; q < 4; q++)
            *reinterpret_cast<uint4*>(sm + SM_A + (ar + 32 * q) * 144 + aj * 16) = ra[q];
#pragma unroll
        for (int q = 0; q < 2; q++)
            *reinterpret_cast<uint4*>(sm + SM_B + (ar + 32 * q) * 144 + aj * 16) = rb[q];
        __syncthreads();

#pragma unroll
        for (int ks = 0; ks < 4; ks++) {
            const int kb2 = ks * 32;
            uint32_t a_f[4];
            ldsm4(a_f, aA + kb2);
            uint32_t bf[8][2];
#pragma unroll
            for (int p = 0; p < 4; p++) {
                uint32_t r4[4];
                ldsm4(r4, aB + p * 16 * 144 + kb2);
                bf[2 * p][0] = r4[0]; bf[2 * p][1] = r4[1];
                bf[2 * p + 1][0] = r4[2]; bf[2 * p + 1][1] = r4[3];
            }
#pragma unroll
            for (int nt = 0; nt < 8; nt++)
                mma16816h(acc[nt], a_f, bf[nt]);
        }
    }

    const int row0 = m0 + w * 16 + (lane >> 2);
    const int cb   = 2 * (lane & 3);
#pragma unroll
    for (int nt = 0; nt < 8; nt++) {
        *reinterpret_cast<float2*>(out + (size_t)row0 * FF + 8 * nt + cb) =
            make_float2(acc[nt][0], acc[nt][1]);
        *reinterpret_cast<float2*>(out + (size_t)(row0 + 8) * FF + 8 * nt + cb) =
            make_float2(acc[nt][2], acc[nt][3]);
    }
}

extern "C" void kernel_launch(void* const* d_in, const int* in_sizes, int n_in,
                              void* d_out, int out_size) {
    const float* nodes = (const float*)d_in[0];
    const int*   nlist = (const int*)d_in[1];
    const float* edges = (const float*)d_in[2];
    const float* w     = (const float*)d_in[3];
    float* out = (float*)d_out;
    (void)in_sizes; (void)n_in; (void)out_size;

    cudaFuncSetAttribute(k_stage1,
                         cudaFuncAttributeMaxDynamicSharedMemorySize, S1SMEM);
    cudaFuncSetAttribute(k_stage2,
                         cudaFuncAttributeMaxDynamicSharedMemorySize, SMEM2_SZ);

    k_stage1<<<NT / S1NODES, 256, S1SMEM>>>(nodes, nlist, edges, w);
    k_stage2<<<NT / 128, 256, SMEM2_SZ>>>(out);
}

// round 10
// speedup vs baseline: 2.4505x; 1.0575x over previous
#include <cuda_runtime.h>
#include <cuda_fp16.h>
#include <stdint.h>

// Problem constants
#define BB 2
#define NN 16384
#define KK 32
#define FF 64
#define EE 16
#define NT (BB * NN)      // 32768 nodes
#define SK (FF * EE)      // 1024 = GEMM contraction length

// Scratch (static __device__ arrays — no runtime allocation)
__device__ __align__(16) __half g_S[(size_t)NT * SK];   // 64 MB: S (fp16)
__device__ __align__(16) __half g_B[FF * SK];           // B[n][k] = w2^T (fp16)
__device__ __align__(16) __half g_Gh[(size_t)NT * FF];  // 4 MB: nodes in fp16

static __device__ __forceinline__ uint32_t hfpack(float hi, float lo) {
    uint32_t r;
    asm("cvt.rn.f16x2.f32 %0, %1, %2;" : "=r"(r) : "f"(hi), "f"(lo));
    return r;
}
static __device__ __forceinline__ uint32_t smem_u32(const void* p) {
    uint32_t a;
    asm("{ .reg .u64 t; cvta.to.shared.u64 t, %1; cvt.u32.u64 %0, t; }" : "=r"(a) : "l"(p));
    return a;
}
static __device__ __forceinline__ void ldsm4(uint32_t* r, uint32_t addr) {
    asm volatile("ldmatrix.sync.aligned.m8n8.x4.shared.b16 {%0,%1,%2,%3}, [%4];"
                 : "=r"(r[0]), "=r"(r[1]), "=r"(r[2]), "=r"(r[3]) : "r"(addr));
}
static __device__ __forceinline__ void ldsm4t(uint32_t* r, uint32_t addr) {
    asm volatile("ldmatrix.sync.aligned.m8n8.x4.trans.shared.b16 {%0,%1,%2,%3}, [%4];"
                 : "=r"(r[0]), "=r"(r[1]), "=r"(r[2]), "=r"(r[3]) : "r"(addr));
}
static __device__ __forceinline__ void mma16816h(float* c, const uint32_t* a,
                                                 const uint32_t* b) {
    asm volatile(
        "mma.sync.aligned.m16n8k16.row.col.f32.f16.f16.f32 "
        "{%0,%1,%2,%3}, {%4,%5,%6,%7}, {%8,%9}, {%0,%1,%2,%3};"
        : "+f"(c[0]), "+f"(c[1]), "+f"(c[2]), "+f"(c[3])
        : "r"(a[0]), "r"(a[1]), "r"(a[2]), "r"(a[3]), "r"(b[0]), "r"(b[1]));
}

// ---- kernel 0: nodes -> fp16 (g_Gh), plus W2 transpose -> g_B (fp16) ----
// Rounding of nodes to fp16 here is bit-identical to the per-gather cvt it
// replaces (same cvt.rn), so numerics are unchanged.
__global__ __launch_bounds__(256) void k_conv(
    const float* __restrict__ nodes, const float* __restrict__ w)
{
    int t = blockIdx.x * 256 + threadIdx.x;          // 0 .. 524287
    float4 v = reinterpret_cast<const float4*>(nodes)[t];
    reinterpret_cast<uint2*>(g_Gh)[t] =
        make_uint2(hfpack(v.y, v.x), hfpack(v.w, v.z));
    if (t < FF * SK) {                               // id = n*1024 + k
        int n = t >> 10;
        int k = t & 1023;
        int l = k >> 4;
        int e = k & 15;
        g_B[t] = __float2half(w[l * (FF * EE) + n * EE + e]);
    }
}

// ---- kernel 1 (tensor): per node, S[64l][16n] = sum_j G[j][l] * (E[j][n]/32) ----
// One warp per node; G gathered pre-converted fp16 (128B/row, half the L2
// traffic), E converted inline. Single-product fp16 HMMA.
#define S1NODES 8
#define GP 144                    // G row pitch bytes (128 data + 16 pad)
#define EP 48                     // E row pitch bytes (32 data + 16 pad)
#define GBYTES (32 * GP)          // 4608
#define EBYTES (32 * EP)          // 1536
#define NODE_SM (GBYTES + EBYTES)           // 6144
#define S1SMEM (S1NODES * NODE_SM)          // 49152

__global__ __launch_bounds__(256) void k_stage1(
    const int*   __restrict__ nlist,
    const float* __restrict__ edges)
{
    extern __shared__ __align__(16) char sm1[];
    const int t    = threadIdx.x;
    const int warp = t >> 5;
    const int lane = t & 31;
    const int g    = blockIdx.x * S1NODES + warp;
    const int b    = g >> 14;

    char* base = sm1 + warp * NODE_SM;
    const uint32_t sb = smem_u32(base);

    const int my_idx = nlist[(size_t)g * KK + lane];
    const __half* nbase = g_Gh + (size_t)b * (NN * FF);

    // ---- gather G (fp16): 32 rows x 128B; 8 lanes/row, 4 rows per pass.
    //      Batch all 8 LDG.128 before the stores for MLP. ----
    const int l4   = lane & 7;     // 16B unit within row
    const int rsub = lane >> 3;    // row within 4-row pass
    {
        uint4 gv[8];
#pragma unroll
        for (int p = 0; p < 8; p++) {
            int j = p * 4 + rsub;
            int jdx = __shfl_sync(0xffffffffu, my_idx, j);
            gv[p] = *reinterpret_cast<const uint4*>(
                nbase + (size_t)jdx * FF + l4 * 8);
        }
#pragma unroll
        for (int p = 0; p < 8; p++) {
            int j = p * 4 + rsub;
            *reinterpret_cast<uint4*>(base + j * GP + l4 * 16) = gv[p];
        }
    }
    // ---- E: 32 rows x 16 floats, scaled by 1/32 (exact), fp16 ----
    {
        const float4* ef = reinterpret_cast<const float4*>(edges) + (size_t)g * 128;
#pragma unroll
        for (int q = 0; q < 4; q++) {
            int u = q * 32 + lane;
            float4 v = ef[u];
            int j = u >> 2, n4 = u & 3;
            *reinterpret_cast<uint2*>(base + GBYTES + j * EP + n4 * 8) =
                make_uint2(hfpack(v.y * 0.03125f, v.x * 0.03125f),
                           hfpack(v.w * 0.03125f, v.z * 0.03125f));
        }
    }
    __syncwarp();

    // ldmatrix.trans addresses (PTX fragment layouts):
    // A (m=l, k=j) from G[j][l]; B (k=j, n=n) from E[j][n]
    const uint32_t aA = sb + ((lane & 7) + 8 * (lane >> 4)) * GP
                           + ((lane >> 3) & 1) * 16;
    const uint32_t aB = sb + GBYTES
                           + ((lane & 7) + 8 * ((lane >> 3) & 1)) * EP
                           + (lane >> 4) * 16;

    float C[4][2][4];
#pragma unroll
    for (int mt = 0; mt < 4; mt++)
#pragma unroll
        for (int nt = 0; nt < 2; nt++)
#pragma unroll
            for (int i = 0; i < 4; i++) C[mt][nt][i] = 0.0f;

#pragma unroll
    for (int ks = 0; ks < 2; ks++) {
        uint32_t bh[4];                       // [0..1]=ntile0, [2..3]=ntile1
        ldsm4t(bh, aB + ks * 16 * EP);
#pragma unroll
        for (int mt = 0; mt < 4; mt++) {
            uint32_t ah[4];
            ldsm4t(ah, aA + ks * 16 * GP + mt * 32);
            mma16816h(C[mt][0], ah, bh);
            mma16816h(C[mt][1], ah, bh + 2);
        }
    }

    // ---- epilogue: pack fp16, stage in smem (reuse G region), STG.128 ----
    __syncwarp();
    __half* sstage = reinterpret_cast<__half*>(base);
    const int r = lane >> 2, q = lane & 3;
#pragma unroll
    for (int mt = 0; mt < 4; mt++) {
#pragma unroll
        for (int nt = 0; nt < 2; nt++) {
            int k0 = (mt * 16 + r) * 16 + nt * 8 + 2 * q;       // (c0,c1)
            *reinterpret_cast<uint32_t*>(sstage + k0) =
                hfpack(C[mt][nt][1], C[mt][nt][0]);
            *reinterpret_cast<uint32_t*>(sstage + k0 + 128) =
                hfpack(C[mt][nt][3], C[mt][nt][2]);
        }
    }
    __syncwarp();
    {
        uint4* dst = reinterpret_cast<uint4*>(g_S + (size_t)g * SK);
        const uint4* src = reinterpret_cast<const uint4*>(sstage);
#pragma unroll
        for (int u = 0; u < 4; u++)
            dst[u * 32 + lane] = src[u * 32 + lane];
    }
}

// ---- kernel 2: HMMA GEMM out[32768 x 64] = S(fp16) @ W2(fp16) ----
// M-tile 256 per block (8 warps x 32 rows): per k-step 6 LDSM feed 16 MMAs.
#define KC 64
#define SM2_A 0
#define SM2_B (256 * 144)                    // 36864
#define SMEM2_SZ (SM2_B + 64 * 144)          // 46080

__global__ __launch_bounds__(256) void k_stage2(float* __restrict__ out)
{
    extern __shared__ __align__(16) char sm[];
    const int t    = threadIdx.x;
    const int w    = t >> 5;
    const int lane = t & 31;
    const int m0   = blockIdx.x * 256;
    const uint32_t sb = smem_u32(sm);

    const int a_r = (lane & 7) + ((lane >> 3) & 1) * 8;
    const int a_k = (lane >> 4) * 8;
    const int b_n = 8 * (lane >> 4) + (lane & 7);
    const int b_k = 8 * ((lane >> 3) & 1);
    const uint32_t aA0 = sb + SM2_A + (w * 32 + a_r) * 144 + a_k * 2;
    const uint32_t aA1 = aA0 + 16 * 144;
    const uint32_t aB  = sb + SM2_B + b_n * 144 + b_k * 2;

    const int ar = t >> 3;          // 0..31
    const int aj = t & 7;

    float acc[2][8][4];
#pragma unroll
    for (int s = 0; s < 2; s++)
#pragma unroll
        for (int nt = 0; nt < 8; nt++)
#pragma unroll
            for (int i = 0; i < 4; i++) acc[s][nt][i] = 0.0f;

    for (int c = 0; c < SK / KC; c++) {
        const int kk = c * KC;
        uint4 ra[8], rb[2];
#pragma unroll
        for (int q = 0; q < 8; q++) {
            size_t src = (size_t)(m0 + ar + 32 * q) * SK + kk + aj * 8;
            ra[q] = *reinterpret_cast<const uint4*>(g_S + src);
        }
#pragma unroll
        for (int q = 0; q < 2; q++) {
            size_t src = (size_t)(ar + 32 * q) * SK + kk + aj * 8;
            rb[q] = *reinterpret_cast<const uint4*>(g_B + src);
        }
        __syncthreads();
#pragma unroll
        for (int q = 0; q < 8; q++)
            *reinterpret_cast<uint4*>(sm + SM2_A + (ar + 32 * q) * 144 + aj * 16) = ra[q];
#pragma unroll
        for (int q = 0; q < 2; q++)
            *reinterpret_cast<uint4*>(sm + SM2_B + (ar + 32 * q) * 144 + aj * 16) = rb[q];
        __syncthreads();

#pragma unroll
        for (int ks = 0; ks < 4; ks++) {
            const int kb2 = ks * 32;
            uint32_t a0[4], a1[4];
            ldsm4(a0, aA0 + kb2);
            ldsm4(a1, aA1 + kb2);
            uint32_t bf[8][2];
#pragma unroll
            for (int p = 0; p < 4; p++) {
                uint32_t r4[4];
                ldsm4(r4, aB + p * 16 * 144 + kb2);
                bf[2 * p][0] = r4[0]; bf[2 * p][1] = r4[1];
                bf[2 * p + 1][0] = r4[2]; bf[2 * p + 1][1] = r4[3];
            }
#pragma unroll
            for (int nt = 0; nt < 8; nt++) {
                mma16816h(acc[0][nt], a0, bf[nt]);
                mma16816h(acc[1][nt], a1, bf[nt]);
            }
        }
    }

    const int cb = 2 * (lane & 3);
#pragma unroll
    for (int s = 0; s < 2; s++) {
        const int row0 = m0 + w * 32 + s * 16 + (lane >> 2);
#pragma unroll
        for (int nt = 0; nt < 8; nt++) {
            *reinterpret_cast<float2*>(out + (size_t)row0 * FF + 8 * nt + cb) =
                make_float2(acc[s][nt][0], acc[s][nt][1]);
            *reinterpret_cast<float2*>(out + (size_t)(row0 + 8) * FF + 8 * nt + cb) =
                make_float2(acc[s][nt][2], acc[s][nt][3]);
        }
    }
}

extern "C" void kernel_launch(void* const* d_in, const int* in_sizes, int n_in,
                              void* d_out, int out_size) {
    const float* nodes = (const float*)d_in[0];
    const int*   nlist = (const int*)d_in[1];
    const float* edges = (const float*)d_in[2];
    const float* w     = (const float*)d_in[3];
    float* out = (float*)d_out;
    (void)in_sizes; (void)n_in; (void)out_size;

    cudaFuncSetAttribute(k_stage1,
                         cudaFuncAttributeMaxDynamicSharedMemorySize, S1SMEM);
    cudaFuncSetAttribute(k_stage2,
                         cudaFuncAttributeMaxDynamicSharedMemorySize, SMEM2_SZ);

    k_conv<<<NT * FF / 4 / 256, 256>>>(nodes, w);
    k_stage1<<<NT / S1NODES, 256, S1SMEM>>>(nlist, edges);
    k_stage2<<<NT / 256, 256, SMEM2_SZ>>>(out);
}